// round 1
// baseline (speedup 1.0000x reference)
#include <cuda_runtime.h>
#include <math.h>

#define BB 8
#define NN 8192
#define MM 4096
#define HH 128
#define WW 128

#define TPB 256
#define TILE 4096

__device__ float g_mean[BB];

// ---------------- per-batch mean of yc_on ----------------
__global__ void mean_kernel(const float* __restrict__ yc_on) {
    int b = blockIdx.x;
    const float* p = yc_on + (size_t)b * HH * WW;
    float s = 0.f;
    for (int i = threadIdx.x; i < HH * WW; i += blockDim.x) s += p[i];
    __shared__ float sh[32];
    #pragma unroll
    for (int o = 16; o; o >>= 1) s += __shfl_down_sync(0xffffffffu, s, o);
    if ((threadIdx.x & 31) == 0) sh[threadIdx.x >> 5] = s;
    __syncthreads();
    if (threadIdx.x < 32) {
        s = (threadIdx.x < (blockDim.x >> 5)) ? sh[threadIdx.x] : 0.f;
        #pragma unroll
        for (int o = 16; o; o >>= 1) s += __shfl_down_sync(0xffffffffu, s, o);
        if (threadIdx.x == 0) g_mean[b] = s * (1.0f / (HH * WW));
    }
}

// ---------------- fused NN-argmin + bilinear + mix ----------------
__global__ void __launch_bounds__(TPB) fused_kernel(
    const float* __restrict__ xc_off,  // (B,N,2)
    const float* __restrict__ yc_off,  // (B,N)
    const float* __restrict__ yc_on,   // (B,H,W)
    const float* __restrict__ xt,      // (B,M,2)
    const float* __restrict__ logit,   // scalar
    float* __restrict__ out)           // (B,M)
{
    const int blocksPerBatch = MM / TPB;
    const int b = blockIdx.x / blocksPerBatch;
    const int m = (blockIdx.x % blocksPerBatch) * TPB + threadIdx.x;

    const float2* cpts = (const float2*)(xc_off + (size_t)b * NN * 2);
    const float2  p    = ((const float2*)(xt + (size_t)b * MM * 2))[m];

    __shared__ float scx[TILE];
    __shared__ float scy[TILE];

    float best = 3.402823466e+38f;
    int   bidx = 0;

    for (int t = 0; t < NN; t += TILE) {
        __syncthreads();
        for (int j = threadIdx.x; j < TILE; j += TPB) {
            float2 c = cpts[t + j];
            scx[j] = c.x;
            scy[j] = c.y;
        }
        __syncthreads();
        #pragma unroll 8
        for (int j = 0; j < TILE; ++j) {
            float dx = p.x - scx[j];
            float dy = p.y - scy[j];
            // match reference rounding: square each, then add (no FMA contraction)
            float d2 = __fadd_rn(__fmul_rn(dx, dx), __fmul_rn(dy, dy));
            bool lt = d2 < best;            // strict <  => first-occurrence argmin
            best = lt ? d2 : best;
            bidx = lt ? (t + j) : bidx;
        }
    }

    float yt_off = yc_off[(size_t)b * NN + bidx];

    // ---- bilinear on uniform [0,1]^2 grid (H=W=128) ----
    float x = p.x, y = p.y;
    bool oob = (x < 0.0f) || (x > 1.0f) || (y < 0.0f) || (y > 1.0f);
    float fx = x * 127.0f;
    float fy = y * 127.0f;
    int ix = (int)floorf(fx);
    int iy = (int)floorf(fy);
    ix = min(max(ix, 0), 126);
    iy = min(max(iy, 0), 126);
    float wx = fx - (float)ix;
    float wy = fy - (float)iy;

    const float* v = yc_on + ((size_t)b * HH + ix) * WW + iy;
    float v00 = v[0];
    float v01 = v[1];
    float v10 = v[WW];
    float v11 = v[WW + 1];

    float yt_on = (1.0f - wx) * (1.0f - wy) * v00
                + (1.0f - wx) * wy          * v01
                + wx          * (1.0f - wy) * v10
                + wx          * wy          * v11;
    if (oob) yt_on = g_mean[b];

    float lg  = logit[0];
    float mix = 1.0f / (1.0f + expf(-lg));
    out[(size_t)b * MM + m] = mix * yt_off + (1.0f - mix) * yt_on;
}

extern "C" void kernel_launch(void* const* d_in, const int* in_sizes, int n_in,
                              void* d_out, int out_size) {
    const float* xc_off = (const float*)d_in[0];  // (8,8192,2)
    const float* yc_off = (const float*)d_in[1];  // (8,8192)
    // d_in[2] = xc_on_grid (unused: analytic uniform grid)
    const float* yc_on  = (const float*)d_in[3];  // (8,128,128)
    const float* xt     = (const float*)d_in[4];  // (8,4096,2)
    const float* logit  = (const float*)d_in[5];  // scalar
    float* out = (float*)d_out;

    mean_kernel<<<BB, 256>>>(yc_on);
    fused_kernel<<<BB * (MM / TPB), TPB>>>(xc_off, yc_off, yc_on, xt, logit, out);
}

// round 2
// speedup vs baseline: 1.6450x; 1.6450x over previous
#include <cuda_runtime.h>
#include <math.h>

#define BB 8
#define NN 8192
#define MM 4096
#define HH 128
#define WW 128

#define TPB 256
#define TILE 4096

__device__ float g_mean[BB];

// ---------------- per-batch mean of yc_on ----------------
__global__ void mean_kernel(const float* __restrict__ yc_on) {
    int b = blockIdx.x;
    const float* p = yc_on + (size_t)b * HH * WW;
    float s = 0.f;
    for (int i = threadIdx.x; i < HH * WW; i += blockDim.x) s += p[i];
    __shared__ float sh[32];
    #pragma unroll
    for (int o = 16; o; o >>= 1) s += __shfl_down_sync(0xffffffffu, s, o);
    if ((threadIdx.x & 31) == 0) sh[threadIdx.x >> 5] = s;
    __syncthreads();
    if (threadIdx.x < 32) {
        s = (threadIdx.x < (blockDim.x >> 5)) ? sh[threadIdx.x] : 0.f;
        #pragma unroll
        for (int o = 16; o; o >>= 1) s += __shfl_down_sync(0xffffffffu, s, o);
        if (threadIdx.x == 0) g_mean[b] = s * (1.0f / (HH * WW));
    }
}

__device__ __forceinline__ unsigned long long pack2(float lo, float hi) {
    unsigned long long r;
    asm("mov.b64 %0, {%1, %2};" : "=l"(r) : "f"(lo), "f"(hi));
    return r;
}
__device__ __forceinline__ void unpack2(unsigned long long v, float& lo, float& hi) {
    asm("mov.b64 {%0, %1}, %2;" : "=f"(lo), "=f"(hi) : "l"(v));
}

// ---------------- fused NN-argmin + bilinear + mix ----------------
__global__ void __launch_bounds__(TPB) fused_kernel(
    const float* __restrict__ xc_off,  // (B,N,2)
    const float* __restrict__ yc_off,  // (B,N)
    const float* __restrict__ yc_on,   // (B,H,W)
    const float* __restrict__ xt,      // (B,M,2)
    const float* __restrict__ logit,   // scalar
    float* __restrict__ out)           // (B,M)
{
    const int blocksPerBatch = MM / TPB;
    const int b = blockIdx.x / blocksPerBatch;
    const int m = (blockIdx.x % blocksPerBatch) * TPB + threadIdx.x;

    const float2* cpts = (const float2*)(xc_off + (size_t)b * NN * 2);
    const float2  p    = ((const float2*)(xt + (size_t)b * MM * 2))[m];

    // negated SoA coords, 8B-aligned for LDS.64 pair loads
    __shared__ __align__(16) float scx[TILE];
    __shared__ __align__(16) float scy[TILE];

    const unsigned long long pxx = pack2(p.x, p.x);
    const unsigned long long pyy = pack2(p.y, p.y);

    float bl = 3.402823466e+38f, bh = 3.402823466e+38f;
    int   jl = 0, jh = 0;

    for (int t = 0; t < NN; t += TILE) {
        __syncthreads();
        for (int j = threadIdx.x; j < TILE; j += TPB) {
            float2 c = cpts[t + j];
            scx[j] = -c.x;
            scy[j] = -c.y;
        }
        __syncthreads();

        const unsigned long long* x2 = (const unsigned long long*)scx;
        const unsigned long long* y2 = (const unsigned long long*)scy;
        const int base = t >> 1;

        #pragma unroll 8
        for (int q = 0; q < TILE / 2; ++q) {
            unsigned long long cx = x2[q];
            unsigned long long cy = y2[q];
            unsigned long long dx, dy, xx, yy, d2;
            // dx = p.x + (-cx)  (exact; per-element .rn == scalar FADD.RN)
            asm("add.rn.f32x2 %0, %1, %2;" : "=l"(dx) : "l"(pxx), "l"(cx));
            asm("add.rn.f32x2 %0, %1, %2;" : "=l"(dy) : "l"(pyy), "l"(cy));
            // square each, then add — matches reference rounding (no FMA)
            asm("mul.rn.f32x2 %0, %1, %2;" : "=l"(xx) : "l"(dx), "l"(dx));
            asm("mul.rn.f32x2 %0, %1, %2;" : "=l"(yy) : "l"(dy), "l"(dy));
            asm("add.rn.f32x2 %0, %1, %2;" : "=l"(d2) : "l"(xx), "l"(yy));

            float dlo, dhi;
            unpack2(d2, dlo, dhi);
            // strict < keeps first occurrence within each parity lane
            if (dlo < bl) { bl = dlo; jl = base + q; }
            if (dhi < bh) { bh = dhi; jh = base + q; }
        }
    }

    // merge even/odd lanes; on exact tie pick the smaller global index
    int idxl = 2 * jl;
    int idxh = 2 * jh + 1;
    int bidx = (bh < bl || (bh == bl && idxh < idxl)) ? idxh : idxl;

    float yt_off = yc_off[(size_t)b * NN + bidx];

    // ---- bilinear on uniform [0,1]^2 grid (H=W=128) ----
    float x = p.x, y = p.y;
    bool oob = (x < 0.0f) || (x > 1.0f) || (y < 0.0f) || (y > 1.0f);
    float fx = x * 127.0f;
    float fy = y * 127.0f;
    int ix = (int)floorf(fx);
    int iy = (int)floorf(fy);
    ix = min(max(ix, 0), 126);
    iy = min(max(iy, 0), 126);
    float wx = fx - (float)ix;
    float wy = fy - (float)iy;

    const float* v = yc_on + ((size_t)b * HH + ix) * WW + iy;
    float v00 = v[0];
    float v01 = v[1];
    float v10 = v[WW];
    float v11 = v[WW + 1];

    float yt_on = (1.0f - wx) * (1.0f - wy) * v00
                + (1.0f - wx) * wy          * v01
                + wx          * (1.0f - wy) * v10
                + wx          * wy          * v11;
    if (oob) yt_on = g_mean[b];

    float lg  = logit[0];
    float mix = 1.0f / (1.0f + expf(-lg));
    out[(size_t)b * MM + m] = mix * yt_off + (1.0f - mix) * yt_on;
}

extern "C" void kernel_launch(void* const* d_in, const int* in_sizes, int n_in,
                              void* d_out, int out_size) {
    const float* xc_off = (const float*)d_in[0];  // (8,8192,2)
    const float* yc_off = (const float*)d_in[1];  // (8,8192)
    // d_in[2] = xc_on_grid (unused: analytic uniform grid)
    const float* yc_on  = (const float*)d_in[3];  // (8,128,128)
    const float* xt     = (const float*)d_in[4];  // (8,4096,2)
    const float* logit  = (const float*)d_in[5];  // scalar
    float* out = (float*)d_out;

    mean_kernel<<<BB, 256>>>(yc_on);
    fused_kernel<<<BB * (MM / TPB), TPB>>>(xc_off, yc_off, yc_on, xt, logit, out);
}

// round 3
// speedup vs baseline: 1.8885x; 1.1480x over previous
#include <cuda_runtime.h>
#include <math.h>

#define BB 8
#define NN 8192
#define MM 4096
#define HH 128
#define WW 128

#define G   64
#define GC  (G * G)          // 4096 cells per batch
#define TPB 256

__device__ float g_mean[BB];
__device__ int    g_counts[BB * GC];
__device__ int    g_starts[BB * GC];
__device__ int    g_cursor[BB * GC];
__device__ float4 g_pts[BB * NN];     // sorted-by-cell: x, y, pad, idx-as-float-bits

__device__ __forceinline__ int cell_of(float v) {
    int c = (int)(v * (float)G);
    return min(max(c, 0), G - 1);
}

// ---------------- per-batch mean of yc_on ----------------
__global__ void mean_kernel(const float* __restrict__ yc_on) {
    int b = blockIdx.x;
    const float* p = yc_on + (size_t)b * HH * WW;
    float s = 0.f;
    for (int i = threadIdx.x; i < HH * WW; i += blockDim.x) s += p[i];
    __shared__ float sh[32];
    #pragma unroll
    for (int o = 16; o; o >>= 1) s += __shfl_down_sync(0xffffffffu, s, o);
    if ((threadIdx.x & 31) == 0) sh[threadIdx.x >> 5] = s;
    __syncthreads();
    if (threadIdx.x < 32) {
        s = (threadIdx.x < (blockDim.x >> 5)) ? sh[threadIdx.x] : 0.f;
        #pragma unroll
        for (int o = 16; o; o >>= 1) s += __shfl_down_sync(0xffffffffu, s, o);
        if (threadIdx.x == 0) g_mean[b] = s * (1.0f / (HH * WW));
    }
}

// ---------------- binning ----------------
__global__ void zero_kernel() {
    int i = blockIdx.x * blockDim.x + threadIdx.x;
    if (i < BB * GC) g_counts[i] = 0;
}

__global__ void hist_kernel(const float* __restrict__ xc_off) {
    int i = blockIdx.x * blockDim.x + threadIdx.x;
    if (i >= BB * NN) return;
    int b = i / NN;
    float2 c = ((const float2*)xc_off)[i];
    int cell = cell_of(c.x) * G + cell_of(c.y);
    atomicAdd(&g_counts[b * GC + cell], 1);
}

// per-batch exclusive scan of 4096 cell counts (one block per batch)
__global__ void scan_kernel() {
    const int CPT = GC / TPB;   // 16
    int b = blockIdx.x;
    int tid = threadIdx.x;
    int base = b * GC + tid * CPT;

    int cnt[CPT];
    int sum = 0;
    #pragma unroll
    for (int i = 0; i < CPT; ++i) { cnt[i] = g_counts[base + i]; sum += cnt[i]; }

    __shared__ int sh[TPB];
    sh[tid] = sum;
    __syncthreads();
    // Hillis-Steele inclusive scan
    #pragma unroll
    for (int o = 1; o < TPB; o <<= 1) {
        int v = (tid >= o) ? sh[tid - o] : 0;
        __syncthreads();
        sh[tid] += v;
        __syncthreads();
    }
    int off = sh[tid] - sum;   // exclusive prefix

    #pragma unroll
    for (int i = 0; i < CPT; ++i) {
        g_starts[base + i] = off;
        g_cursor[base + i] = off;
        off += cnt[i];
    }
}

__global__ void scatter_kernel(const float* __restrict__ xc_off) {
    int i = blockIdx.x * blockDim.x + threadIdx.x;
    if (i >= BB * NN) return;
    int b = i / NN;
    int n = i - b * NN;
    float2 c = ((const float2*)xc_off)[i];
    int cell = cell_of(c.x) * G + cell_of(c.y);
    int pos = atomicAdd(&g_cursor[b * GC + cell], 1);
    g_pts[(size_t)b * NN + pos] = make_float4(c.x, c.y, 0.f, __int_as_float(n));
}

// ---------------- query: grid NN + bilinear + mix ----------------
__global__ void __launch_bounds__(TPB) query_kernel(
    const float* __restrict__ yc_off,
    const float* __restrict__ yc_on,
    const float* __restrict__ xt,
    const float* __restrict__ logit,
    float* __restrict__ out)
{
    const int blocksPerBatch = MM / TPB;
    const int b = blockIdx.x / blocksPerBatch;
    const int m = (blockIdx.x % blocksPerBatch) * TPB + threadIdx.x;

    const float2 p = ((const float2*)(xt + (size_t)b * MM * 2))[m];
    const int*    starts = g_starts + b * GC;
    const int*    counts = g_counts + b * GC;
    const float4* pts    = g_pts + (size_t)b * NN;

    const float h = 1.0f / (float)G;
    const int qcx = cell_of(p.x);
    const int qcy = cell_of(p.y);

    float best = 3.402823466e+38f;
    int   bidx = 0x7fffffff;

    for (int r = 0; r < G; ++r) {
        int ilo = max(qcx - r, 0), ihi = min(qcx + r, G - 1);
        int jlo = max(qcy - r, 0), jhi = min(qcy + r, G - 1);
        for (int i = ilo; i <= ihi; ++i) {
            bool edgeRow = (i == qcx - r) || (i == qcx + r);
            // on non-edge rows only the two edge columns belong to ring r
            int jstep = edgeRow ? 1 : max(jhi - jlo, 1);
            for (int j = jlo; j <= jhi; j += jstep) {
                if (!edgeRow && j != qcy - r && j != qcy + r) continue;
                int c = i * G + j;
                int s = starts[c];
                int e = s + counts[c];
                for (int k = s; k < e; ++k) {
                    float4 q = pts[k];
                    float dx = p.x - q.x;
                    float dy = p.y - q.y;
                    float d2 = __fadd_rn(__fmul_rn(dx, dx), __fmul_rn(dy, dy));
                    int   idx = __float_as_int(q.w);
                    if (d2 < best || (d2 == best && idx < bidx)) {
                        best = d2;
                        bidx = idx;
                    }
                }
            }
        }
        // pruning bound: distance from p to boundary of searched square ∩ [0,1]^2
        float lox = (float)(qcx - r) * h,     hix = (float)(qcx + r + 1) * h;
        float loy = (float)(qcy - r) * h,     hiy = (float)(qcy + r + 1) * h;
        float bnd = 3.402823466e+38f;
        if (lox > 0.f) bnd = fminf(bnd, p.x - lox);
        if (hix < 1.f) bnd = fminf(bnd, hix - p.x);
        if (loy > 0.f) bnd = fminf(bnd, p.y - loy);
        if (hiy < 1.f) bnd = fminf(bnd, hiy - p.y);
        if (bnd == 3.402823466e+38f) break;                   // whole domain searched
        if (bidx != 0x7fffffff && best < bnd * bnd * 0.99999f) break;
    }

    float yt_off = yc_off[(size_t)b * NN + bidx];

    // ---- bilinear on uniform [0,1]^2 grid (H=W=128) ----
    float x = p.x, y = p.y;
    bool oob = (x < 0.0f) || (x > 1.0f) || (y < 0.0f) || (y > 1.0f);
    float fx = x * 127.0f;
    float fy = y * 127.0f;
    int ix = (int)floorf(fx);
    int iy = (int)floorf(fy);
    ix = min(max(ix, 0), 126);
    iy = min(max(iy, 0), 126);
    float wx = fx - (float)ix;
    float wy = fy - (float)iy;

    const float* v = yc_on + ((size_t)b * HH + ix) * WW + iy;
    float v00 = v[0];
    float v01 = v[1];
    float v10 = v[WW];
    float v11 = v[WW + 1];

    float yt_on = (1.0f - wx) * (1.0f - wy) * v00
                + (1.0f - wx) * wy          * v01
                + wx          * (1.0f - wy) * v10
                + wx          * wy          * v11;
    if (oob) yt_on = g_mean[b];

    float lg  = logit[0];
    float mix = 1.0f / (1.0f + expf(-lg));
    out[(size_t)b * MM + m] = mix * yt_off + (1.0f - mix) * yt_on;
}

extern "C" void kernel_launch(void* const* d_in, const int* in_sizes, int n_in,
                              void* d_out, int out_size) {
    const float* xc_off = (const float*)d_in[0];  // (8,8192,2)
    const float* yc_off = (const float*)d_in[1];  // (8,8192)
    // d_in[2] = xc_on_grid (unused: analytic uniform grid)
    const float* yc_on  = (const float*)d_in[3];  // (8,128,128)
    const float* xt     = (const float*)d_in[4];  // (8,4096,2)
    const float* logit  = (const float*)d_in[5];  // scalar
    float* out = (float*)d_out;

    zero_kernel<<<(BB * GC + 255) / 256, 256>>>();
    mean_kernel<<<BB, 256>>>(yc_on);
    hist_kernel<<<(BB * NN + 255) / 256, 256>>>(xc_off);
    scan_kernel<<<BB, TPB>>>();
    scatter_kernel<<<(BB * NN + 255) / 256, 256>>>(xc_off);
    query_kernel<<<BB * (MM / TPB), TPB>>>(yc_off, yc_on, xt, logit, out);
}

// round 4
// speedup vs baseline: 2.2482x; 1.1905x over previous
#include <cuda_runtime.h>
#include <math.h>

#define BB 8
#define NN 8192
#define MM 4096
#define HH 128
#define WW 128

#define G    64
#define GC   (G * G)           // 4096 cells per batch
#define BTPB 1024              // build kernel threads
#define PPT  (NN / BTPB)       // 8 points per thread
#define CPT  (GC / BTPB)       // 4 cells per thread
#define QTPB 256

__device__ float  g_mean[BB];
__device__ int    g_starts[BB * (GC + 1)];
__device__ float4 g_pts[BB * NN];   // cell-sorted: x, y, pad, orig-idx bits

__device__ __forceinline__ int cell_of(float v) {
    int c = (int)(v * (float)G);
    return min(max(c, 0), G - 1);
}

// ---------- fused per-batch: mean + histogram + scan + scatter ----------
__global__ void __launch_bounds__(BTPB) build_kernel(
    const float* __restrict__ xc_off,   // (B,N,2)
    const float* __restrict__ yc_on)    // (B,H,W)
{
    const int b   = blockIdx.x;
    const int tid = threadIdx.x;

    __shared__ int   scnt[GC];          // counts -> cursors
    __shared__ float swsum[32];
    __shared__ int   swscan[32];

    // ---- zero histogram ----
    #pragma unroll
    for (int i = 0; i < CPT; ++i) scnt[tid + i * BTPB] = 0;

    // ---- mean of yc_on (16384 elems) ----
    {
        const float* p = yc_on + (size_t)b * HH * WW;
        float s = 0.f;
        #pragma unroll
        for (int k = 0; k < (HH * WW) / BTPB; ++k) s += p[tid + k * BTPB];
        #pragma unroll
        for (int o = 16; o; o >>= 1) s += __shfl_down_sync(0xffffffffu, s, o);
        if ((tid & 31) == 0) swsum[tid >> 5] = s;
    }
    __syncthreads();
    if (tid < 32) {
        float s = swsum[tid];
        #pragma unroll
        for (int o = 16; o; o >>= 1) s += __shfl_down_sync(0xffffffffu, s, o);
        if (tid == 0) g_mean[b] = s * (1.0f / (HH * WW));
    }

    // ---- load points to registers + histogram ----
    float2 pt[PPT];
    int    pc[PPT];
    const float2* cpts = (const float2*)(xc_off + (size_t)b * NN * 2);
    #pragma unroll
    for (int k = 0; k < PPT; ++k) {
        pt[k] = cpts[tid + k * BTPB];                 // coalesced
        pc[k] = cell_of(pt[k].x) * G + cell_of(pt[k].y);
        atomicAdd(&scnt[pc[k]], 1);
    }
    __syncthreads();

    // ---- exclusive scan of 4096 counts (4 cells/thread, contiguous) ----
    int c[CPT];
    int sum = 0;
    #pragma unroll
    for (int i = 0; i < CPT; ++i) { c[i] = scnt[tid * CPT + i]; sum += c[i]; }

    int v = sum;
    const int lane = tid & 31, wrp = tid >> 5;
    #pragma unroll
    for (int o = 1; o < 32; o <<= 1) {
        int n = __shfl_up_sync(0xffffffffu, v, o);
        if (lane >= o) v += n;
    }
    if (lane == 31) swscan[wrp] = v;
    __syncthreads();
    if (tid < 32) {
        int w = swscan[tid];
        #pragma unroll
        for (int o = 1; o < 32; o <<= 1) {
            int n = __shfl_up_sync(0xffffffffu, w, o);
            if (tid >= o) w += n;
        }
        swscan[tid] = w;
    }
    __syncthreads();
    int off = v - sum + (wrp ? swscan[wrp - 1] : 0);   // exclusive prefix

    int* starts = g_starts + b * (GC + 1);
    #pragma unroll
    for (int i = 0; i < CPT; ++i) {
        starts[tid * CPT + i] = off;
        c[i] = off;                 // local cursor base
        off += scnt[tid * CPT + i] ? 0 : 0, off = c[i] + scnt[tid * CPT + i] ? off : off; // (no-op; clarity below)
        off = c[i] + scnt[tid * CPT + i];
    }
    if (tid == 0) starts[GC] = NN;
    __syncthreads();

    // overwrite smem counts with cursors
    #pragma unroll
    for (int i = 0; i < CPT; ++i) scnt[tid * CPT + i] = c[i];
    __syncthreads();

    // ---- scatter from registers ----
    float4* dst = g_pts + (size_t)b * NN;
    #pragma unroll
    for (int k = 0; k < PPT; ++k) {
        int pos = atomicAdd(&scnt[pc[k]], 1);
        dst[pos] = make_float4(pt[k].x, pt[k].y, 0.f, __int_as_float(tid + k * BTPB));
    }
}

// ---------------- query: grid NN + bilinear + mix ----------------
__global__ void __launch_bounds__(QTPB) query_kernel(
    const float* __restrict__ yc_off,
    const float* __restrict__ yc_on,
    const float* __restrict__ xt,
    const float* __restrict__ logit,
    float* __restrict__ out)
{
    const int blocksPerBatch = MM / QTPB;
    const int b = blockIdx.x / blocksPerBatch;
    const int m = (blockIdx.x % blocksPerBatch) * QTPB + threadIdx.x;

    const float2 p = ((const float2*)(xt + (size_t)b * MM * 2))[m];
    const int*    starts = g_starts + b * (GC + 1);
    const float4* pts    = g_pts + (size_t)b * NN;

    const float h = 1.0f / (float)G;
    const int qcx = cell_of(p.x);
    const int qcy = cell_of(p.y);

    float best = 3.402823466e+38f;
    int   bidx = 0x7fffffff;

    for (int r = 0; r < G; ++r) {
        int ilo = max(qcx - r, 0), ihi = min(qcx + r, G - 1);
        int jlo = max(qcy - r, 0), jhi = min(qcy + r, G - 1);
        for (int i = ilo; i <= ihi; ++i) {
            bool edgeRow = (i == qcx - r) || (i == qcx + r);
            int jstep = edgeRow ? 1 : max(jhi - jlo, 1);
            for (int j = jlo; j <= jhi; j += jstep) {
                if (!edgeRow && j != qcy - r && j != qcy + r) continue;
                int cc = i * G + j;
                int s = starts[cc];
                int e = starts[cc + 1];
                for (int k = s; k < e; ++k) {
                    float4 q = pts[k];
                    float dx = p.x - q.x;
                    float dy = p.y - q.y;
                    float d2 = __fadd_rn(__fmul_rn(dx, dx), __fmul_rn(dy, dy));
                    int   idx = __float_as_int(q.w);
                    if (d2 < best || (d2 == best && idx < bidx)) {
                        best = d2;
                        bidx = idx;
                    }
                }
            }
        }
        float lox = (float)(qcx - r) * h,  hix = (float)(qcx + r + 1) * h;
        float loy = (float)(qcy - r) * h,  hiy = (float)(qcy + r + 1) * h;
        float bnd = 3.402823466e+38f;
        if (lox > 0.f) bnd = fminf(bnd, p.x - lox);
        if (hix < 1.f) bnd = fminf(bnd, hix - p.x);
        if (loy > 0.f) bnd = fminf(bnd, p.y - loy);
        if (hiy < 1.f) bnd = fminf(bnd, hiy - p.y);
        if (bnd == 3.402823466e+38f) break;
        if (bidx != 0x7fffffff && best < bnd * bnd * 0.99999f) break;
    }

    float yt_off = yc_off[(size_t)b * NN + bidx];

    // ---- bilinear on uniform [0,1]^2 grid ----
    float x = p.x, y = p.y;
    bool oob = (x < 0.0f) || (x > 1.0f) || (y < 0.0f) || (y > 1.0f);
    float fx = x * 127.0f;
    float fy = y * 127.0f;
    int ix = (int)floorf(fx);
    int iy = (int)floorf(fy);
    ix = min(max(ix, 0), 126);
    iy = min(max(iy, 0), 126);
    float wx = fx - (float)ix;
    float wy = fy - (float)iy;

    const float* vv = yc_on + ((size_t)b * HH + ix) * WW + iy;
    float v00 = vv[0];
    float v01 = vv[1];
    float v10 = vv[WW];
    float v11 = vv[WW + 1];

    float yt_on = (1.0f - wx) * (1.0f - wy) * v00
                + (1.0f - wx) * wy          * v01
                + wx          * (1.0f - wy) * v10
                + wx          * wy          * v11;
    if (oob) yt_on = g_mean[b];

    float lg  = logit[0];
    float mix = 1.0f / (1.0f + expf(-lg));
    out[(size_t)b * MM + m] = mix * yt_off + (1.0f - mix) * yt_on;
}

extern "C" void kernel_launch(void* const* d_in, const int* in_sizes, int n_in,
                              void* d_out, int out_size) {
    const float* xc_off = (const float*)d_in[0];  // (8,8192,2)
    const float* yc_off = (const float*)d_in[1];  // (8,8192)
    // d_in[2] = xc_on_grid (unused: analytic uniform grid)
    const float* yc_on  = (const float*)d_in[3];  // (8,128,128)
    const float* xt     = (const float*)d_in[4];  // (8,4096,2)
    const float* logit  = (const float*)d_in[5];  // scalar
    float* out = (float*)d_out;

    build_kernel<<<BB, BTPB>>>(xc_off, yc_on);
    query_kernel<<<BB * (MM / QTPB), QTPB>>>(yc_off, yc_on, xt, logit, out);
}

// round 5
// speedup vs baseline: 3.5699x; 1.5879x over previous
#include <cuda_runtime.h>
#include <math.h>

#define BB 8
#define NN 8192
#define MM 4096
#define HH 128
#define WW 128

#define G    64
#define GC   (G * G)           // 4096 cells per batch
#define BTPB 1024
#define PPT  (NN / BTPB)       // 8 points per thread
#define QPT  (MM / BTPB)       // 4 queries per thread
#define CPT  (GC / BTPB)       // 4 cells per thread
#define QTPB 256

__device__ float  g_mean[BB];
__device__ int    g_starts[BB * (GC + 1)];
__device__ float4 g_pts[BB * NN];   // cell-sorted points: x, y, 0, orig-idx bits
__device__ float4 g_q[BB * MM];     // cell-sorted queries: x, y, 0, orig-m bits

__device__ __forceinline__ int cell_of(float v) {
    int c = (int)(v * (float)G);
    return min(max(c, 0), G - 1);
}

// ---------- fused per-batch: mean + bin points + bin queries ----------
__global__ void __launch_bounds__(BTPB) build_kernel(
    const float* __restrict__ xc_off,   // (B,N,2)
    const float* __restrict__ yc_on,    // (B,H,W)
    const float* __restrict__ xt)       // (B,M,2)
{
    const int b   = blockIdx.x;
    const int tid = threadIdx.x;
    const int lane = tid & 31, wrp = tid >> 5;

    __shared__ int   scnt[GC];
    __shared__ float swsum[32];
    __shared__ int   swscan[32];

    // ---- zero histogram ----
    #pragma unroll
    for (int i = 0; i < CPT; ++i) scnt[tid + i * BTPB] = 0;

    // ---- mean of yc_on ----
    {
        const float* p = yc_on + (size_t)b * HH * WW;
        float s = 0.f;
        #pragma unroll
        for (int k = 0; k < (HH * WW) / BTPB; ++k) s += p[tid + k * BTPB];
        #pragma unroll
        for (int o = 16; o; o >>= 1) s += __shfl_down_sync(0xffffffffu, s, o);
        if (lane == 0) swsum[wrp] = s;
    }
    __syncthreads();
    if (tid < 32) {
        float s = swsum[tid];
        #pragma unroll
        for (int o = 16; o; o >>= 1) s += __shfl_down_sync(0xffffffffu, s, o);
        if (tid == 0) g_mean[b] = s * (1.0f / (HH * WW));
    }

    // ================= pass 1: points =================
    float2 pt[PPT];
    int    pc[PPT];
    {
        const float2* cpts = (const float2*)(xc_off + (size_t)b * NN * 2);
        #pragma unroll
        for (int k = 0; k < PPT; ++k) {
            pt[k] = cpts[tid + k * BTPB];
            pc[k] = cell_of(pt[k].x) * G + cell_of(pt[k].y);
            atomicAdd(&scnt[pc[k]], 1);
        }
    }
    __syncthreads();

    {
        int cnt[CPT], cur[CPT];
        int sum = 0;
        #pragma unroll
        for (int i = 0; i < CPT; ++i) { cnt[i] = scnt[tid * CPT + i]; sum += cnt[i]; }

        int v = sum;
        #pragma unroll
        for (int o = 1; o < 32; o <<= 1) {
            int n = __shfl_up_sync(0xffffffffu, v, o);
            if (lane >= o) v += n;
        }
        if (lane == 31) swscan[wrp] = v;
        __syncthreads();
        if (tid < 32) {
            int w = swscan[tid];
            #pragma unroll
            for (int o = 1; o < 32; o <<= 1) {
                int n = __shfl_up_sync(0xffffffffu, w, o);
                if (tid >= o) w += n;
            }
            swscan[tid] = w;
        }
        __syncthreads();
        int off = v - sum + (wrp ? swscan[wrp - 1] : 0);

        int* starts = g_starts + b * (GC + 1);
        #pragma unroll
        for (int i = 0; i < CPT; ++i) {
            starts[tid * CPT + i] = off;
            cur[i] = off;
            off += cnt[i];
        }
        if (tid == 0) starts[GC] = NN;
        __syncthreads();
        #pragma unroll
        for (int i = 0; i < CPT; ++i) scnt[tid * CPT + i] = cur[i];
    }
    __syncthreads();

    {
        float4* dst = g_pts + (size_t)b * NN;
        #pragma unroll
        for (int k = 0; k < PPT; ++k) {
            int pos = atomicAdd(&scnt[pc[k]], 1);
            dst[pos] = make_float4(pt[k].x, pt[k].y, 0.f, __int_as_float(tid + k * BTPB));
        }
    }
    __syncthreads();

    // ================= pass 2: queries (sort by cell) =================
    #pragma unroll
    for (int i = 0; i < CPT; ++i) scnt[tid + i * BTPB] = 0;
    __syncthreads();

    float2 qt[QPT];
    int    qc[QPT];
    {
        const float2* q = (const float2*)(xt + (size_t)b * MM * 2);
        #pragma unroll
        for (int k = 0; k < QPT; ++k) {
            qt[k] = q[tid + k * BTPB];
            qc[k] = cell_of(qt[k].x) * G + cell_of(qt[k].y);
            atomicAdd(&scnt[qc[k]], 1);
        }
    }
    __syncthreads();

    {
        int cnt[CPT], cur[CPT];
        int sum = 0;
        #pragma unroll
        for (int i = 0; i < CPT; ++i) { cnt[i] = scnt[tid * CPT + i]; sum += cnt[i]; }

        int v = sum;
        #pragma unroll
        for (int o = 1; o < 32; o <<= 1) {
            int n = __shfl_up_sync(0xffffffffu, v, o);
            if (lane >= o) v += n;
        }
        if (lane == 31) swscan[wrp] = v;
        __syncthreads();
        if (tid < 32) {
            int w = swscan[tid];
            #pragma unroll
            for (int o = 1; o < 32; o <<= 1) {
                int n = __shfl_up_sync(0xffffffffu, w, o);
                if (tid >= o) w += n;
            }
            swscan[tid] = w;
        }
        __syncthreads();
        int off = v - sum + (wrp ? swscan[wrp - 1] : 0);

        #pragma unroll
        for (int i = 0; i < CPT; ++i) { cur[i] = off; off += cnt[i]; }
        __syncthreads();
        #pragma unroll
        for (int i = 0; i < CPT; ++i) scnt[tid * CPT + i] = cur[i];
    }
    __syncthreads();

    {
        float4* dst = g_q + (size_t)b * MM;
        #pragma unroll
        for (int k = 0; k < QPT; ++k) {
            int pos = atomicAdd(&scnt[qc[k]], 1);
            dst[pos] = make_float4(qt[k].x, qt[k].y, 0.f, __int_as_float(tid + k * BTPB));
        }
    }
}

// ---------------- query: grid NN (sorted queries) + bilinear + mix ----------------
__global__ void __launch_bounds__(QTPB) query_kernel(
    const float* __restrict__ yc_off,
    const float* __restrict__ yc_on,
    const float* __restrict__ logit,
    float* __restrict__ out)
{
    const int t = blockIdx.x * QTPB + threadIdx.x;   // global sorted-query index
    const int b = t / MM;

    const float4 q = g_q[t];
    const float2 p = make_float2(q.x, q.y);
    const int    m = __float_as_int(q.w);

    const int*    starts = g_starts + b * (GC + 1);
    const float4* pts    = g_pts + (size_t)b * NN;

    const float h = 1.0f / (float)G;
    const int qcx = cell_of(p.x);
    const int qcy = cell_of(p.y);

    float best = 3.402823466e+38f;
    int   bidx = 0x7fffffff;

    // ---- fast path: 3x3 neighborhood, start bounds hoisted (MLP) ----
    {
        const int ilo = max(qcx - 1, 0), ihi = min(qcx + 1, G - 1);
        const int jlo = max(qcy - 1, 0), jhi = min(qcy + 1, G - 1);
        int s0 = 0, e0 = 0, s1 = 0, e1 = 0, s2 = 0, e2 = 0;
        const int nrows = ihi - ilo + 1;
        s0 = starts[ilo * G + jlo];           e0 = starts[ilo * G + jhi + 1];
        if (nrows > 1) { s1 = starts[(ilo + 1) * G + jlo]; e1 = starts[(ilo + 1) * G + jhi + 1]; }
        if (nrows > 2) { s2 = starts[(ilo + 2) * G + jlo]; e2 = starts[(ilo + 2) * G + jhi + 1]; }

        #pragma unroll 1
        for (int rr = 0; rr < 3; ++rr) {
            int s = (rr == 0) ? s0 : (rr == 1 ? s1 : s2);
            int e = (rr == 0) ? e0 : (rr == 1 ? e1 : e2);
            #pragma unroll 4
            for (int k = s; k < e; ++k) {
                float4 c = pts[k];
                float dx = p.x - c.x;
                float dy = p.y - c.y;
                float d2 = __fadd_rn(__fmul_rn(dx, dx), __fmul_rn(dy, dy));
                int   idx = __float_as_int(c.w);
                if (d2 < best || (d2 == best && idx < bidx)) { best = d2; bidx = idx; }
            }
        }
    }

    // ---- bound check + rare expansion (full-square rescan, idempotent) ----
    for (int r = 1; ; ++r) {
        float lox = (float)(qcx - r) * h,  hix = (float)(qcx + r + 1) * h;
        float loy = (float)(qcy - r) * h,  hiy = (float)(qcy + r + 1) * h;
        float bnd = 3.402823466e+38f;
        if (lox > 0.f) bnd = fminf(bnd, p.x - lox);
        if (hix < 1.f) bnd = fminf(bnd, hix - p.x);
        if (loy > 0.f) bnd = fminf(bnd, p.y - loy);
        if (hiy < 1.f) bnd = fminf(bnd, hiy - p.y);
        if (bnd == 3.402823466e+38f) break;
        if (bidx != 0x7fffffff && best < bnd * bnd * 0.99999f) break;

        const int r2 = r + 1;
        const int ilo = max(qcx - r2, 0), ihi = min(qcx + r2, G - 1);
        const int jlo = max(qcy - r2, 0), jhi = min(qcy + r2, G - 1);
        for (int i = ilo; i <= ihi; ++i) {
            int s = starts[i * G + jlo];
            int e = starts[i * G + jhi + 1];
            for (int k = s; k < e; ++k) {
                float4 c = pts[k];
                float dx = p.x - c.x;
                float dy = p.y - c.y;
                float d2 = __fadd_rn(__fmul_rn(dx, dx), __fmul_rn(dy, dy));
                int   idx = __float_as_int(c.w);
                if (d2 < best || (d2 == best && idx < bidx)) { best = d2; bidx = idx; }
            }
        }
    }

    float yt_off = yc_off[(size_t)b * NN + bidx];

    // ---- bilinear on uniform [0,1]^2 grid ----
    float x = p.x, y = p.y;
    bool oob = (x < 0.0f) || (x > 1.0f) || (y < 0.0f) || (y > 1.0f);
    float fx = x * 127.0f;
    float fy = y * 127.0f;
    int ix = (int)floorf(fx);
    int iy = (int)floorf(fy);
    ix = min(max(ix, 0), 126);
    iy = min(max(iy, 0), 126);
    float wx = fx - (float)ix;
    float wy = fy - (float)iy;

    const float* vv = yc_on + ((size_t)b * HH + ix) * WW + iy;
    float v00 = vv[0];
    float v01 = vv[1];
    float v10 = vv[WW];
    float v11 = vv[WW + 1];

    float yt_on = (1.0f - wx) * (1.0f - wy) * v00
                + (1.0f - wx) * wy          * v01
                + wx          * (1.0f - wy) * v10
                + wx          * wy          * v11;
    if (oob) yt_on = g_mean[b];

    float lg  = logit[0];
    float mix = 1.0f / (1.0f + expf(-lg));
    out[(size_t)b * MM + m] = mix * yt_off + (1.0f - mix) * yt_on;
}

extern "C" void kernel_launch(void* const* d_in, const int* in_sizes, int n_in,
                              void* d_out, int out_size) {
    const float* xc_off = (const float*)d_in[0];  // (8,8192,2)
    const float* yc_off = (const float*)d_in[1];  // (8,8192)
    // d_in[2] = xc_on_grid (unused: analytic uniform grid)
    const float* yc_on  = (const float*)d_in[3];  // (8,128,128)
    const float* xt     = (const float*)d_in[4];  // (8,4096,2)
    const float* logit  = (const float*)d_in[5];  // scalar
    float* out = (float*)d_out;

    build_kernel<<<BB, BTPB>>>(xc_off, yc_on, xt);
    query_kernel<<<BB * MM / QTPB, QTPB>>>(yc_off, yc_on, logit, out);
}

// round 6
// speedup vs baseline: 3.8462x; 1.0774x over previous
#include <cuda_runtime.h>
#include <math.h>

#define BB 8
#define NN 8192
#define MM 4096
#define HH 128
#define WW 128

#define G    64
#define GC   (G * G)           // 4096 cells per batch
#define BTPB 1024
#define PPT  (NN / BTPB)       // 8 points per thread
#define QPT  (MM / BTPB)       // 4 queries per thread
#define CPT  (GC / BTPB)       // 4 cells per thread
#define QTPB 128

__device__ float  g_mean[BB];
__device__ int    g_starts[BB * (GC + 1)];
__device__ float4 g_pts[BB * NN];   // cell-sorted points: x, y, 0, orig-idx bits
__device__ float4 g_q[BB * MM];     // cell-sorted queries: x, y, 0, orig-m bits

__device__ __forceinline__ int cell_of(float v) {
    int c = (int)(v * (float)G);
    return min(max(c, 0), G - 1);
}

// exclusive scan of GC counts living in scnt[], returns per-thread cursors c[CPT]
// (thread owns cells tid*CPT .. tid*CPT+CPT-1). Also optionally writes g_starts.
__device__ __forceinline__ void scan_counts(int* scnt, int* swscan, int tid,
                                            int lane, int wrp, int* cur,
                                            int* starts /* may be null */) {
    int cnt[CPT];
    int sum = 0;
    #pragma unroll
    for (int i = 0; i < CPT; ++i) { cnt[i] = scnt[tid * CPT + i]; sum += cnt[i]; }

    int v = sum;
    #pragma unroll
    for (int o = 1; o < 32; o <<= 1) {
        int n = __shfl_up_sync(0xffffffffu, v, o);
        if (lane >= o) v += n;
    }
    if (lane == 31) swscan[wrp] = v;
    __syncthreads();
    if (tid < 32) {
        int w = swscan[tid];
        #pragma unroll
        for (int o = 1; o < 32; o <<= 1) {
            int n = __shfl_up_sync(0xffffffffu, w, o);
            if (tid >= o) w += n;
        }
        swscan[tid] = w;
    }
    __syncthreads();
    int off = v - sum + (wrp ? swscan[wrp - 1] : 0);

    #pragma unroll
    for (int i = 0; i < CPT; ++i) {
        if (starts) starts[tid * CPT + i] = off;
        cur[i] = off;
        off += cnt[i];
    }
    __syncthreads();
    #pragma unroll
    for (int i = 0; i < CPT; ++i) scnt[tid * CPT + i] = cur[i];
    __syncthreads();
}

// ---------- build: 2 independent blocks per batch ----------
// role 0: bin context points  -> g_starts, g_pts
// role 1: mean + bin queries  -> g_mean, g_q
__global__ void __launch_bounds__(BTPB) build_kernel(
    const float* __restrict__ xc_off,   // (B,N,2)
    const float* __restrict__ yc_on,    // (B,H,W)
    const float* __restrict__ xt)       // (B,M,2)
{
    const int b    = blockIdx.x >> 1;
    const int role = blockIdx.x & 1;
    const int tid  = threadIdx.x;
    const int lane = tid & 31, wrp = tid >> 5;

    __shared__ int scnt[GC];
    __shared__ int swscan[32];

    #pragma unroll
    for (int i = 0; i < CPT; ++i) scnt[tid + i * BTPB] = 0;

    if (role == 0) {
        // ---- context points ----
        float2 pt[PPT];
        int    pc[PPT];
        const float2* cpts = (const float2*)(xc_off + (size_t)b * NN * 2);
        #pragma unroll
        for (int k = 0; k < PPT; ++k) {
            pt[k] = cpts[tid + k * BTPB];
            pc[k] = cell_of(pt[k].x) * G + cell_of(pt[k].y);
        }
        __syncthreads();   // histogram zero visible
        #pragma unroll
        for (int k = 0; k < PPT; ++k) atomicAdd(&scnt[pc[k]], 1);
        __syncthreads();

        int cur[CPT];
        scan_counts(scnt, swscan, tid, lane, wrp, cur, g_starts + b * (GC + 1));
        if (tid == 0) g_starts[b * (GC + 1) + GC] = NN;

        float4* dst = g_pts + (size_t)b * NN;
        #pragma unroll
        for (int k = 0; k < PPT; ++k) {
            int pos = atomicAdd(&scnt[pc[k]], 1);
            dst[pos] = make_float4(pt[k].x, pt[k].y, 0.f, __int_as_float(tid + k * BTPB));
        }
    } else {
        // ---- mean of yc_on ----
        __shared__ float swsum[32];
        {
            const float* p = yc_on + (size_t)b * HH * WW;
            float s = 0.f;
            #pragma unroll
            for (int k = 0; k < (HH * WW) / BTPB; ++k) s += p[tid + k * BTPB];
            #pragma unroll
            for (int o = 16; o; o >>= 1) s += __shfl_down_sync(0xffffffffu, s, o);
            if (lane == 0) swsum[wrp] = s;
        }

        // ---- queries ----
        float2 qt[QPT];
        int    qc[QPT];
        const float2* q = (const float2*)(xt + (size_t)b * MM * 2);
        #pragma unroll
        for (int k = 0; k < QPT; ++k) {
            qt[k] = q[tid + k * BTPB];
            qc[k] = cell_of(qt[k].x) * G + cell_of(qt[k].y);
        }
        __syncthreads();   // histogram zero + swsum visible
        if (tid < 32) {
            float s = swsum[tid];
            #pragma unroll
            for (int o = 16; o; o >>= 1) s += __shfl_down_sync(0xffffffffu, s, o);
            if (tid == 0) g_mean[b] = s * (1.0f / (HH * WW));
        }
        #pragma unroll
        for (int k = 0; k < QPT; ++k) atomicAdd(&scnt[qc[k]], 1);
        __syncthreads();

        int cur[CPT];
        scan_counts(scnt, swscan, tid, lane, wrp, cur, (int*)0);

        float4* dst = g_q + (size_t)b * MM;
        #pragma unroll
        for (int k = 0; k < QPT; ++k) {
            int pos = atomicAdd(&scnt[qc[k]], 1);
            dst[pos] = make_float4(qt[k].x, qt[k].y, 0.f, __int_as_float(tid + k * BTPB));
        }
    }
}

// ---------------- query: grid NN (sorted queries) + bilinear + mix ----------------
__global__ void __launch_bounds__(QTPB) query_kernel(
    const float* __restrict__ yc_off,
    const float* __restrict__ yc_on,
    const float* __restrict__ logit,
    float* __restrict__ out)
{
    const int t = blockIdx.x * QTPB + threadIdx.x;   // global sorted-query index
    const int b = t / MM;

    const float4 q = g_q[t];
    const float2 p = make_float2(q.x, q.y);
    const int    m = __float_as_int(q.w);

    const int*    starts = g_starts + b * (GC + 1);
    const float4* pts    = g_pts + (size_t)b * NN;

    // ---- bilinear first: its 4 loads overlap the NN-scan latency ----
    float yt_on;
    {
        float x = p.x, y = p.y;
        bool oob = (x < 0.0f) || (x > 1.0f) || (y < 0.0f) || (y > 1.0f);
        float fx = x * 127.0f;
        float fy = y * 127.0f;
        int ix = (int)floorf(fx);
        int iy = (int)floorf(fy);
        ix = min(max(ix, 0), 126);
        iy = min(max(iy, 0), 126);
        float wx = fx - (float)ix;
        float wy = fy - (float)iy;

        const float* vv = yc_on + ((size_t)b * HH + ix) * WW + iy;
        float v00 = vv[0];
        float v01 = vv[1];
        float v10 = vv[WW];
        float v11 = vv[WW + 1];

        yt_on = (1.0f - wx) * (1.0f - wy) * v00
              + (1.0f - wx) * wy          * v01
              + wx          * (1.0f - wy) * v10
              + wx          * wy          * v11;
        if (oob) yt_on = g_mean[b];
    }

    const float h = 1.0f / (float)G;
    const int qcx = cell_of(p.x);
    const int qcy = cell_of(p.y);

    float best = 3.402823466e+38f;
    int   bidx = 0x7fffffff;

    // ---- fast path: 3x3 neighborhood, segment bounds hoisted (MLP) ----
    {
        const int ilo = max(qcx - 1, 0), ihi = min(qcx + 1, G - 1);
        const int jlo = max(qcy - 1, 0), jhi = min(qcy + 1, G - 1);
        int s0 = 0, e0 = 0, s1 = 0, e1 = 0, s2 = 0, e2 = 0;
        const int nrows = ihi - ilo + 1;
        s0 = starts[ilo * G + jlo];           e0 = starts[ilo * G + jhi + 1];
        if (nrows > 1) { s1 = starts[(ilo + 1) * G + jlo]; e1 = starts[(ilo + 1) * G + jhi + 1]; }
        if (nrows > 2) { s2 = starts[(ilo + 2) * G + jlo]; e2 = starts[(ilo + 2) * G + jhi + 1]; }

        #pragma unroll 1
        for (int rr = 0; rr < 3; ++rr) {
            int s = (rr == 0) ? s0 : (rr == 1 ? s1 : s2);
            int e = (rr == 0) ? e0 : (rr == 1 ? e1 : e2);
            #pragma unroll 4
            for (int k = s; k < e; ++k) {
                float4 c = pts[k];
                float dx = p.x - c.x;
                float dy = p.y - c.y;
                float d2 = __fadd_rn(__fmul_rn(dx, dx), __fmul_rn(dy, dy));
                int   idx = __float_as_int(c.w);
                if (d2 < best || (d2 == best && idx < bidx)) { best = d2; bidx = idx; }
            }
        }
    }

    // ---- bound check + rare expansion (scan only the NEW perimeter ring) ----
    for (int r = 1; ; ++r) {
        float lox = (float)(qcx - r) * h,  hix = (float)(qcx + r + 1) * h;
        float loy = (float)(qcy - r) * h,  hiy = (float)(qcy + r + 1) * h;
        float bnd = 3.402823466e+38f;
        if (lox > 0.f) bnd = fminf(bnd, p.x - lox);
        if (hix < 1.f) bnd = fminf(bnd, hix - p.x);
        if (loy > 0.f) bnd = fminf(bnd, p.y - loy);
        if (hiy < 1.f) bnd = fminf(bnd, hiy - p.y);
        if (bnd == 3.402823466e+38f) break;
        if (bidx != 0x7fffffff && best < bnd * bnd * 0.99999f) break;

        const int rn = r + 1;
        const int jlo = max(qcy - rn, 0), jhi = min(qcy + rn, G - 1);
        const int itop = qcx - rn, ibot = qcx + rn;

        // top/bottom edge rows: full segment
        #pragma unroll 1
        for (int e2i = 0; e2i < 2; ++e2i) {
            int i = e2i ? ibot : itop;
            if (i < 0 || i > G - 1) continue;
            int s = starts[i * G + jlo];
            int e = starts[i * G + jhi + 1];
            for (int k = s; k < e; ++k) {
                float4 c = pts[k];
                float dx = p.x - c.x;
                float dy = p.y - c.y;
                float d2 = __fadd_rn(__fmul_rn(dx, dx), __fmul_rn(dy, dy));
                int   idx = __float_as_int(c.w);
                if (d2 < best || (d2 == best && idx < bidx)) { best = d2; bidx = idx; }
            }
        }
        // interior rows: only the two new edge columns
        const int iil = max(itop + 1, 0), iih = min(ibot - 1, G - 1);
        const int jL = qcy - rn, jR = qcy + rn;
        #pragma unroll 1
        for (int i = iil; i <= iih; ++i) {
            #pragma unroll 1
            for (int e2j = 0; e2j < 2; ++e2j) {
                int j = e2j ? jR : jL;
                if (j < 0 || j > G - 1) continue;
                int cc = i * G + j;
                int s = starts[cc];
                int e = starts[cc + 1];
                for (int k = s; k < e; ++k) {
                    float4 c = pts[k];
                    float dx = p.x - c.x;
                    float dy = p.y - c.y;
                    float d2 = __fadd_rn(__fmul_rn(dx, dx), __fmul_rn(dy, dy));
                    int   idx = __float_as_int(c.w);
                    if (d2 < best || (d2 == best && idx < bidx)) { best = d2; bidx = idx; }
                }
            }
        }
    }

    float yt_off = yc_off[(size_t)b * NN + bidx];

    float lg  = logit[0];
    float mix = 1.0f / (1.0f + expf(-lg));
    out[(size_t)b * MM + m] = mix * yt_off + (1.0f - mix) * yt_on;
}

extern "C" void kernel_launch(void* const* d_in, const int* in_sizes, int n_in,
                              void* d_out, int out_size) {
    const float* xc_off = (const float*)d_in[0];  // (8,8192,2)
    const float* yc_off = (const float*)d_in[1];  // (8,8192)
    // d_in[2] = xc_on_grid (unused: analytic uniform grid)
    const float* yc_on  = (const float*)d_in[3];  // (8,128,128)
    const float* xt     = (const float*)d_in[4];  // (8,4096,2)
    const float* logit  = (const float*)d_in[5];  // scalar
    float* out = (float*)d_out;

    build_kernel<<<BB * 2, BTPB>>>(xc_off, yc_on, xt);
    query_kernel<<<BB * MM / QTPB, QTPB>>>(yc_off, yc_on, logit, out);
}